// round 11
// baseline (speedup 1.0000x reference)
#include <cuda_runtime.h>
#include <cuda_fp16.h>
#include <cstdint>

namespace {

constexpr int B_ = 8, H_ = 64, W_ = 64, C_ = 128, N_ = 9, F_ = 256;
constexpr int THREADS = 256;
constexpr int NSTAGE  = 18;               // stages of K=64 (2 chunks of 32)
constexpr int PADP    = 36;               // A stride in b32 pairs (32 data + 4 pad)

// dynamic smem layout (b32 units)
constexpr int A_SZ    = 64 * PADP;        // 2304 words per A buffer (64 px x 64 ch)
constexpr int A0_OFF  = 0;
constexpr int A1_OFF  = A_SZ;
constexpr int C4_OFF  = 2 * A_SZ;                   // int4 per (tap,pixel)
constexpr int FY_OFF  = C4_OFF + 4 * N_ * 64;
constexpr int FX_OFF  = FY_OFF + N_ * 64;
constexpr int SMEM_WORDS = FX_OFF + N_ * 64;
constexpr int SMEM_BYTES = SMEM_WORDS * 4;          // ~32.8 KB

constexpr int W_CH = 32 * 32 * 4;         // 4096 words per chunk W image

// Faithful reproduction of reference (2,3,3)->(9,2) reshape order
__constant__ int c_iy[9] = {0, 0, 1, 2, 2, 1, 0, 2, 1};
__constant__ int c_ix[9] = {0, 1, 1, 2, 0, 2, 1, 0, 2};

// fp16 copy of x: [b][y][x][c]
__device__ __half g_xh[B_ * H_ * W_ * C_];
// W fragment image (fp16 pairs): [k(36)][ft(32)][lane(32)][ks(2)][j(2)]
__device__ uint32_t g_Wimg[36 * W_CH];

__device__ __forceinline__ uint32_t pack2(float a, float b) {
    __half2 h = __floats2half2_rn(a, b);
    return *reinterpret_cast<uint32_t*>(&h);
}
__device__ __forceinline__ uint32_t smem_u32(const void* p) {
    uint32_t a;
    asm("{ .reg .u64 t; cvta.to.shared.u64 t, %1; cvt.u32.u64 %0, t; }" : "=r"(a) : "l"(p));
    return a;
}
__device__ __forceinline__ void mma_f16(float* c, const uint32_t* a, uint32_t b0, uint32_t b1) {
    asm volatile(
        "mma.sync.aligned.m16n8k16.row.col.f32.f16.f16.f32 "
        "{%0,%1,%2,%3}, {%4,%5,%6,%7}, {%8,%9}, {%0,%1,%2,%3};"
        : "+f"(c[0]), "+f"(c[1]), "+f"(c[2]), "+f"(c[3])
        : "r"(a[0]), "r"(a[1]), "r"(a[2]), "r"(a[3]), "r"(b0), "r"(b1));
}
__device__ __forceinline__ void ldsm_x4(uint32_t* r, uint32_t addr) {
    asm volatile("ldmatrix.sync.aligned.m8n8.x4.shared.b16 {%0,%1,%2,%3}, [%4];"
                 : "=r"(r[0]), "=r"(r[1]), "=r"(r[2]), "=r"(r[3]) : "r"(addr));
}

// half2 bilinear lerp of 8 channels
__device__ __forceinline__ uint4 lerp8h(uint4 lt, uint4 rt, uint4 lb, uint4 rb,
                                        uint32_t fy2u, uint32_t fx2u) {
    const __half2 fy2 = *reinterpret_cast<__half2*>(&fy2u);
    const __half2 fx2 = *reinterpret_cast<__half2*>(&fx2u);
    uint4 o;
    const uint32_t* pl = (const uint32_t*)&lt;
    const uint32_t* pr = (const uint32_t*)&rt;
    const uint32_t* ql = (const uint32_t*)&lb;
    const uint32_t* qr = (const uint32_t*)&rb;
    uint32_t* po = (uint32_t*)&o;
    #pragma unroll
    for (int w = 0; w < 4; w++) {
        __half2 LT = *reinterpret_cast<const __half2*>(pl + w);
        __half2 RT = *reinterpret_cast<const __half2*>(pr + w);
        __half2 LB = *reinterpret_cast<const __half2*>(ql + w);
        __half2 RB = *reinterpret_cast<const __half2*>(qr + w);
        __half2 t = __hfma2(__hsub2(RT, LT), fy2, LT);
        __half2 b = __hfma2(__hsub2(RB, LB), fy2, LB);
        __half2 m = __hfma2(__hsub2(b, t), fx2, t);
        po[w] = *reinterpret_cast<uint32_t*>(&m);
    }
    return o;
}

// ---------------- merged prep kernel: x->fp16 and W fragment image ----------------
// blocks [0,2048): convert x (8 floats/thread). blocks [2048,2624): build W image.
__global__ void prep_kernel(const float* __restrict__ x, const float* __restrict__ Wt) {
    const int blk = blockIdx.x;
    const int tid = threadIdx.x;
    if (blk < 2048) {
        int i = (blk * 256 + tid) * 8;
        float4 v0 = *(const float4*)(x + i);
        float4 v1 = *(const float4*)(x + i + 4);
        uint4 o;
        o.x = pack2(v0.x, v0.y);
        o.y = pack2(v0.z, v0.w);
        o.z = pack2(v1.x, v1.y);
        o.w = pack2(v1.z, v1.w);
        *(uint4*)(g_xh + i) = o;
    } else {
        int idx = (blk - 2048) * 256 + tid;          // 0 .. 36*W_CH-1
        int j    = idx & 1;
        int ks   = (idx >> 1) & 1;
        int lane = (idx >> 2) & 31;
        int ft   = (idx >> 7) & 31;
        int k    = idx >> 12;                        // chunk 0..35
        int n    = k >> 2;
        int cc   = k & 3;
        int gq = lane >> 2, tq = lane & 3;
        int f  = ft * 8 + gq;
        int c0 = cc * 32 + ks * 16 + j * 8 + tq * 2;
        float w0 = Wt[((size_t)n * C_ + c0) * F_ + f];
        float w1 = Wt[((size_t)n * C_ + c0 + 1) * F_ + f];
        g_Wimg[idx] = pack2(w0, w1);
    }
}

// ---------------- main fused kernel ----------------
__global__ __launch_bounds__(THREADS, 2)
void deform_mma_kernel(const float* __restrict__ offs,
                       const float* __restrict__ bias,
                       float* __restrict__ out) {
    extern __shared__ float smf[];
    uint32_t* A_buf[2] = { (uint32_t*)smf + A0_OFF, (uint32_t*)smf + A1_OFF };
    int4*     s_c4  = (int4*)(smf + C4_OFF);
    uint32_t* s_fy2 = (uint32_t*)smf + FY_OFF;
    uint32_t* s_fx2 = (uint32_t*)smf + FX_OFF;

    const uint32_t a_smem[2] = { smem_u32(A_buf[0]), smem_u32(A_buf[1]) };

    const int tid  = threadIdx.x;
    const int wid  = tid >> 5;
    const int lane = tid & 31;
    const int wr   = wid >> 2;        // warp row (0..1): m base = wr*32
    const int wc   = wid & 3;         // warp col (0..3): f base = wc*64
    const int gq   = lane >> 2;
    const int tq   = lane & 3;

    // ldmatrix lane offset within the warp's A block (words)
    const int lrow = (lane & 7) + ((lane >> 3) & 1) * 8;
    const int lcol = (lane >> 4) * 4;
    const uint32_t a_frag_off = (uint32_t)(((wr * 32 + lrow) * PADP + lcol) * 4);

    // B fragment global pointer base: uint4 index (k*32 + wc*8 + ni)*32 + lane
    const uint4* __restrict__ Wg = (const uint4*)g_Wimg + (size_t)(wc * 8) * 32 + lane;

    const int blk = blockIdx.x;       // b*64 + h
    const int b   = blk >> 6;
    const int h   = blk & 63;
    const __half* img = g_xh + (size_t)b * H_ * W_ * C_;

    const int c8  = tid & 3;          // 8-channel slice within 32-ch chunk
    const int pix = tid >> 2;         // 0..63

    // ---- precompute corner offsets + fractions for all 9 taps ----
    for (int e = tid; e < N_ * 64; e += THREADS) {
        const int n  = e >> 6;
        const int ww = e & 63;
        const float* orow = offs + (((size_t)blk * 64 + ww) * (2 * N_));
        float cy = (float)(h - 1 + c_iy[n]) + orow[2 * n];
        float cx = (float)(ww - 1 + c_ix[n]) + orow[2 * n + 1];
        cy = fminf(fmaxf(cy, 0.0f), 63.0f);
        cx = fminf(fmaxf(cx, 0.0f), 63.0f);
        float y0f = floorf(cy);
        float x0f = floorf(cx);
        const int y0 = (int)y0f;
        const int x0 = (int)x0f;
        const int y1 = min(y0 + 1, 63);
        const int x1 = min(x0 + 1, 63);
        int4 c4;
        c4.x = (y0 * 64 + x0) << 7;   // lt
        c4.y = (y1 * 64 + x0) << 7;   // rt
        c4.z = (y0 * 64 + x1) << 7;   // lb
        c4.w = (y1 * 64 + x1) << 7;   // rb
        s_c4[e]  = c4;
        const float fy = cy - y0f, fx = cx - x0f;
        s_fy2[e] = pack2(fy, fy);
        s_fx2[e] = pack2(fx, fx);
    }
    __syncthreads();

    float acc[2][8][4];
    #pragma unroll
    for (int mi = 0; mi < 2; mi++)
        #pragma unroll
        for (int ni = 0; ni < 8; ni++)
            #pragma unroll
            for (int r = 0; r < 4; r++) acc[mi][ni][r] = 0.0f;

    // ---- prologue: stage chunks 0,1 (tap 0) into A_buf[0] ----
    {
        const int4 c4 = s_c4[pix];
        const uint32_t fy2 = s_fy2[pix], fx2 = s_fx2[pix];
        #pragma unroll
        for (int cpos = 0; cpos < 2; cpos++) {
            const int c_off = cpos * 32 + c8 * 8;
            uint4 lt = *(const uint4*)(img + c4.x + c_off);
            uint4 rt = *(const uint4*)(img + c4.y + c_off);
            uint4 lb = *(const uint4*)(img + c4.z + c_off);
            uint4 rb = *(const uint4*)(img + c4.w + c_off);
            *(uint4*)(A_buf[0] + pix * PADP + cpos * 16 + c8 * 4) =
                lerp8h(lt, rt, lb, rb, fy2, fx2);
        }
    }

    // ---- main stage loop: 18 stages of K=64 ----
    #pragma unroll 1
    for (int s = 0; s < NSTAGE; s++) {
        __syncthreads();     // A(s) visible; A(s-1) reads done -> buffer reusable

        const int buf  = s & 1;
        const int nbuf = buf ^ 1;
        const bool more = (s + 1 < NSTAGE);

        int4 c4;
        uint32_t fy2 = 0, fx2 = 0;
        uint4 lt, rt, lb, rb;
        int cbase = 0;
        if (more) {
            const int k0 = 2 * s + 2;           // first chunk staged this stage
            const int e  = (k0 >> 2) * 64 + pix;
            c4  = s_c4[e];
            fy2 = s_fy2[e];
            fx2 = s_fx2[e];
            cbase = (k0 & 3) * 32 + c8 * 8;
            lt = *(const uint4*)(img + c4.x + cbase);
            rt = *(const uint4*)(img + c4.y + cbase);
            lb = *(const uint4*)(img + c4.z + cbase);
            rb = *(const uint4*)(img + c4.w + cbase);
        }

        const uint32_t a_base = a_smem[buf] + a_frag_off;
        const uint4* __restrict__ wp0 = Wg + (size_t)(2 * s) * 1024;

        // ---- MMA chunk cpos=0 (k = 2s) ----
        {
            uint32_t a[2][2][4];
            #pragma unroll
            for (int mi = 0; mi < 2; mi++) {
                ldsm_x4(a[0][mi], a_base + (uint32_t)((mi * 16 * PADP) * 4));
                ldsm_x4(a[1][mi], a_base + (uint32_t)((mi * 16 * PADP + 8) * 4));
            }
            #pragma unroll
            for (int ni = 0; ni < 8; ni++) {
                uint4 bv = wp0[ni * 32];
                mma_f16(acc[0][ni], a[0][0], bv.x, bv.y);
                mma_f16(acc[1][ni], a[0][1], bv.x, bv.y);
                mma_f16(acc[0][ni], a[1][0], bv.z, bv.w);
                mma_f16(acc[1][ni], a[1][1], bv.z, bv.w);
            }
        }

        if (more) {
            // finish staging first chunk; start loads for second
            *(uint4*)(A_buf[nbuf] + pix * PADP + c8 * 4) =
                lerp8h(lt, rt, lb, rb, fy2, fx2);
            const int c_off = cbase + 32;
            lt = *(const uint4*)(img + c4.x + c_off);
            rt = *(const uint4*)(img + c4.y + c_off);
            lb = *(const uint4*)(img + c4.z + c_off);
            rb = *(const uint4*)(img + c4.w + c_off);
        }

        // ---- MMA chunk cpos=1 (k = 2s+1) ----
        {
            const uint4* __restrict__ wp1 = wp0 + 1024;
            uint32_t a[2][2][4];
            #pragma unroll
            for (int mi = 0; mi < 2; mi++) {
                ldsm_x4(a[0][mi], a_base + (uint32_t)((mi * 16 * PADP + 16) * 4));
                ldsm_x4(a[1][mi], a_base + (uint32_t)((mi * 16 * PADP + 24) * 4));
            }
            #pragma unroll
            for (int ni = 0; ni < 8; ni++) {
                uint4 bv = wp1[ni * 32];
                mma_f16(acc[0][ni], a[0][0], bv.x, bv.y);
                mma_f16(acc[1][ni], a[0][1], bv.x, bv.y);
                mma_f16(acc[0][ni], a[1][0], bv.z, bv.w);
                mma_f16(acc[1][ni], a[1][1], bv.z, bv.w);
            }
        }

        if (more) {
            *(uint4*)(A_buf[nbuf] + pix * PADP + 16 + c8 * 4) =
                lerp8h(lt, rt, lb, rb, fy2, fx2);
        }
    }

    // ---- epilogue: add bias, store ----
    #pragma unroll
    for (int mi = 0; mi < 2; mi++) {
        const int row0 = wr * 32 + mi * 16 + gq;
        float* o0 = out + ((size_t)blk * 64 + row0) * F_;
        float* o1 = o0 + 8 * F_;
        #pragma unroll
        for (int ni = 0; ni < 8; ni++) {
            const int f = wc * 64 + ni * 8 + tq * 2;
            const float2 bb = *(const float2*)(bias + f);
            float2 r0, r1;
            r0.x = acc[mi][ni][0] + bb.x;
            r0.y = acc[mi][ni][1] + bb.y;
            r1.x = acc[mi][ni][2] + bb.x;
            r1.y = acc[mi][ni][3] + bb.y;
            *(float2*)(o0 + f) = r0;
            *(float2*)(o1 + f) = r1;
        }
    }
}

}  // namespace

extern "C" void kernel_launch(void* const* d_in, const int* in_sizes, int n_in,
                              void* d_out, int out_size) {
    (void)in_sizes; (void)n_in; (void)out_size;
    const float* x    = (const float*)d_in[0];   // (8,64,64,128)
    const float* offs = (const float*)d_in[1];   // (8,64,64,18)
    const float* Wt   = (const float*)d_in[2];   // (9,128,256)
    const float* bias = (const float*)d_in[3];   // (256,)
    float* out = (float*)d_out;                  // (8,64,64,256)

    cudaFuncSetAttribute(deform_mma_kernel,
                         cudaFuncAttributeMaxDynamicSharedMemorySize, SMEM_BYTES);

    prep_kernel<<<2048 + (36 * W_CH) / 256, 256>>>(x, Wt);
    deform_mma_kernel<<<B_ * H_, THREADS, SMEM_BYTES>>>(offs, bias, out);
}

// round 12
// speedup vs baseline: 1.2497x; 1.2497x over previous
#include <cuda_runtime.h>
#include <cuda_fp16.h>
#include <cstdint>

namespace {

constexpr int B_ = 8, H_ = 64, W_ = 64, C_ = 128, N_ = 9, F_ = 256;
constexpr int THREADS = 256;
constexpr int NSTAGE  = 18;               // stages of K=64 (2 chunks of 32)
constexpr int PADP    = 36;               // A row stride in b32 words (32 data + 4 pad)
constexpr int MPX     = 32;               // pixels per CTA

// dynamic smem layout (b32 units)
constexpr int A_SZ    = MPX * PADP;       // 1152 words per A buffer (32 px x 64 ch fp16)
constexpr int A0_OFF  = 0;
constexpr int A1_OFF  = A_SZ;
constexpr int C4_OFF  = 2 * A_SZ;                   // int4 per (tap,pixel)
constexpr int FY_OFF  = C4_OFF + 4 * N_ * MPX;
constexpr int FX_OFF  = FY_OFF + N_ * MPX;
constexpr int SMEM_WORDS = FX_OFF + N_ * MPX;
constexpr int SMEM_BYTES = SMEM_WORDS * 4;          // ~16.1 KB

constexpr int W_CH = 32 * 32 * 4;         // 4096 words per chunk W image

// Faithful reproduction of reference (2,3,3)->(9,2) reshape order
__constant__ int c_iy[9] = {0, 0, 1, 2, 2, 1, 0, 2, 1};
__constant__ int c_ix[9] = {0, 1, 1, 2, 0, 2, 1, 0, 2};

// fp16 copy of x: [b][y][x][c]
__device__ __half g_xh[B_ * H_ * W_ * C_];
// W fragment image (fp16 pairs): [k(36)][ft(32)][lane(32)][ks(2)][j(2)]
__device__ uint32_t g_Wimg[36 * W_CH];

__device__ __forceinline__ uint32_t pack2(float a, float b) {
    __half2 h = __floats2half2_rn(a, b);
    return *reinterpret_cast<uint32_t*>(&h);
}
__device__ __forceinline__ uint32_t smem_u32(const void* p) {
    uint32_t a;
    asm("{ .reg .u64 t; cvta.to.shared.u64 t, %1; cvt.u32.u64 %0, t; }" : "=r"(a) : "l"(p));
    return a;
}
__device__ __forceinline__ void mma_f16(float* c, uint32_t a0, uint32_t a1, uint32_t a2,
                                        uint32_t a3, uint32_t b0, uint32_t b1) {
    asm volatile(
        "mma.sync.aligned.m16n8k16.row.col.f32.f16.f16.f32 "
        "{%0,%1,%2,%3}, {%4,%5,%6,%7}, {%8,%9}, {%0,%1,%2,%3};"
        : "+f"(c[0]), "+f"(c[1]), "+f"(c[2]), "+f"(c[3])
        : "r"(a0), "r"(a1), "r"(a2), "r"(a3), "r"(b0), "r"(b1));
}
__device__ __forceinline__ void ldsm_x4(uint32_t* r, uint32_t addr) {
    asm volatile("ldmatrix.sync.aligned.m8n8.x4.shared.b16 {%0,%1,%2,%3}, [%4];"
                 : "=r"(r[0]), "=r"(r[1]), "=r"(r[2]), "=r"(r[3]) : "r"(addr));
}

// half2 bilinear lerp of 8 channels
__device__ __forceinline__ uint4 lerp8h(uint4 lt, uint4 rt, uint4 lb, uint4 rb,
                                        uint32_t fy2u, uint32_t fx2u) {
    const __half2 fy2 = *reinterpret_cast<__half2*>(&fy2u);
    const __half2 fx2 = *reinterpret_cast<__half2*>(&fx2u);
    uint4 o;
    const uint32_t* pl = (const uint32_t*)&lt;
    const uint32_t* pr = (const uint32_t*)&rt;
    const uint32_t* ql = (const uint32_t*)&lb;
    const uint32_t* qr = (const uint32_t*)&rb;
    uint32_t* po = (uint32_t*)&o;
    #pragma unroll
    for (int w = 0; w < 4; w++) {
        __half2 LT = *reinterpret_cast<const __half2*>(pl + w);
        __half2 RT = *reinterpret_cast<const __half2*>(pr + w);
        __half2 LB = *reinterpret_cast<const __half2*>(ql + w);
        __half2 RB = *reinterpret_cast<const __half2*>(qr + w);
        __half2 t = __hfma2(__hsub2(RT, LT), fy2, LT);
        __half2 b = __hfma2(__hsub2(RB, LB), fy2, LB);
        __half2 m = __hfma2(__hsub2(b, t), fx2, t);
        po[w] = *reinterpret_cast<uint32_t*>(&m);
    }
    return o;
}

// ---------------- merged prep kernel ----------------
__global__ void prep_kernel(const float* __restrict__ x, const float* __restrict__ Wt) {
    const int blk = blockIdx.x;
    const int tid = threadIdx.x;
    if (blk < 2048) {
        int i = (blk * 256 + tid) * 8;
        float4 v0 = *(const float4*)(x + i);
        float4 v1 = *(const float4*)(x + i + 4);
        uint4 o;
        o.x = pack2(v0.x, v0.y);
        o.y = pack2(v0.z, v0.w);
        o.z = pack2(v1.x, v1.y);
        o.w = pack2(v1.z, v1.w);
        *(uint4*)(g_xh + i) = o;
    } else {
        int idx = (blk - 2048) * 256 + tid;          // 0 .. 36*W_CH-1
        int j    = idx & 1;
        int ks   = (idx >> 1) & 1;
        int lane = (idx >> 2) & 31;
        int ft   = (idx >> 7) & 31;
        int k    = idx >> 12;                        // chunk 0..35
        int n    = k >> 2;
        int cc   = k & 3;
        int gq = lane >> 2, tq = lane & 3;
        int f  = ft * 8 + gq;
        int c0 = cc * 32 + ks * 16 + j * 8 + tq * 2;
        float w0 = Wt[((size_t)n * C_ + c0) * F_ + f];
        float w1 = Wt[((size_t)n * C_ + c0 + 1) * F_ + f];
        g_Wimg[idx] = pack2(w0, w1);
    }
}

// ---------------- main fused kernel ----------------
__global__ __launch_bounds__(THREADS, 3)
void deform_mma_kernel(const float* __restrict__ offs,
                       const float* __restrict__ bias,
                       float* __restrict__ out) {
    extern __shared__ float smf[];
    uint32_t* A_buf[2] = { (uint32_t*)smf + A0_OFF, (uint32_t*)smf + A1_OFF };
    int4*     s_c4  = (int4*)(smf + C4_OFF);
    uint32_t* s_fy2 = (uint32_t*)smf + FY_OFF;
    uint32_t* s_fx2 = (uint32_t*)smf + FX_OFF;

    const uint32_t a_smem[2] = { smem_u32(A_buf[0]), smem_u32(A_buf[1]) };

    const int tid  = threadIdx.x;
    const int wid  = tid >> 5;        // warp -> f block: f = wid*32 .. +31
    const int lane = tid & 31;
    const int gq   = lane >> 2;
    const int tq   = lane & 3;

    // ldmatrix lane offset within the A tile (words)
    const int lrow = (lane & 7) + ((lane >> 3) & 1) * 8;
    const int lcol = (lane >> 4) * 4;
    const uint32_t a_frag_off = (uint32_t)((lrow * PADP + lcol) * 4);

    // B fragment global pointer base (uint4 units): (k*32 + wid*4 + ni)*32 + lane
    const uint4* __restrict__ Wg = (const uint4*)g_Wimg + (size_t)(wid * 4) * 32 + lane;

    const int blk = blockIdx.x;             // 1024 CTAs; pixel base = blk*32
    const int pbase = blk * MPX;
    const int b   = pbase >> 12;
    const __half* img = g_xh + (size_t)b * H_ * W_ * C_;

    const int c8  = tid & 7;          // 8-channel slice within stage's 64 ch
    const int pix = tid >> 3;         // 0..31

    // ---- precompute corner offsets + fractions for all 9 taps x 32 pixels ----
    for (int e = tid; e < N_ * MPX; e += THREADS) {
        const int n  = e >> 5;
        const int lp = e & 31;
        const int p  = pbase + lp;
        const int hh = (p >> 6) & 63;
        const int ww = p & 63;
        const float* orow = offs + (size_t)p * (2 * N_);
        float cy = (float)(hh - 1 + c_iy[n]) + orow[2 * n];
        float cx = (float)(ww - 1 + c_ix[n]) + orow[2 * n + 1];
        cy = fminf(fmaxf(cy, 0.0f), 63.0f);
        cx = fminf(fmaxf(cx, 0.0f), 63.0f);
        float y0f = floorf(cy);
        float x0f = floorf(cx);
        const int y0 = (int)y0f;
        const int x0 = (int)x0f;
        const int y1 = min(y0 + 1, 63);
        const int x1 = min(x0 + 1, 63);
        int4 c4;
        c4.x = (y0 * 64 + x0) << 7;   // lt
        c4.y = (y1 * 64 + x0) << 7;   // rt
        c4.z = (y0 * 64 + x1) << 7;   // lb
        c4.w = (y1 * 64 + x1) << 7;   // rb
        s_c4[e]  = c4;
        const float fy = cy - y0f, fx = cx - x0f;
        s_fy2[e] = pack2(fy, fy);
        s_fx2[e] = pack2(fx, fx);
    }
    __syncthreads();

    float acc[2][4][4];               // [mi][ni][reg]
    #pragma unroll
    for (int mi = 0; mi < 2; mi++)
        #pragma unroll
        for (int ni = 0; ni < 4; ni++)
            #pragma unroll
            for (int r = 0; r < 4; r++) acc[mi][ni][r] = 0.0f;

    // ---- prologue: stage s=0 (tap 0, channels 0..63) into A_buf[0] ----
    {
        const int4 c4 = s_c4[pix];
        const int c_off = c8 * 8;
        uint4 lt = *(const uint4*)(img + c4.x + c_off);
        uint4 rt = *(const uint4*)(img + c4.y + c_off);
        uint4 lb = *(const uint4*)(img + c4.z + c_off);
        uint4 rb = *(const uint4*)(img + c4.w + c_off);
        *(uint4*)(A_buf[0] + pix * PADP + c8 * 4) =
            lerp8h(lt, rt, lb, rb, s_fy2[pix], s_fx2[pix]);
    }

    // ---- main stage loop: 18 stages of K=64 ----
    #pragma unroll 1
    for (int s = 0; s < NSTAGE; s++) {
        __syncthreads();     // A(s) visible; A(s-1) reads done -> other buffer reusable

        const int buf  = s & 1;
        const int nbuf = buf ^ 1;
        const bool more = (s + 1 < NSTAGE);

        // prefetch corners for stage s+1
        uint4 lt, rt, lb, rb;
        uint32_t fy2 = 0, fx2 = 0;
        if (more) {
            const int s1 = s + 1;
            const int e  = (s1 >> 1) * MPX + pix;     // tap = s1/2
            const int4 c4 = s_c4[e];
            fy2 = s_fy2[e];
            fx2 = s_fx2[e];
            const int c_off = (s1 & 1) * 64 + c8 * 8;
            lt = *(const uint4*)(img + c4.x + c_off);
            rt = *(const uint4*)(img + c4.y + c_off);
            lb = *(const uint4*)(img + c4.z + c_off);
            rb = *(const uint4*)(img + c4.w + c_off);
        }

        const uint32_t a_base = a_smem[buf] + a_frag_off;
        const uint4* __restrict__ wp = Wg + (size_t)(2 * s) * 1024;

        // ---- MMA half kh=0 (chunk 2s) ----
        {
            uint32_t a0[4], a1[4], a2[4], a3[4];
            ldsm_x4(a0, a_base);                                   // mi0, ks0
            ldsm_x4(a1, a_base + (uint32_t)(16 * PADP * 4));       // mi1, ks0
            ldsm_x4(a2, a_base + 8u * 4u);                         // mi0, ks1
            ldsm_x4(a3, a_base + (uint32_t)((16 * PADP + 8) * 4)); // mi1, ks1
            #pragma unroll
            for (int ni = 0; ni < 4; ni++) {
                uint4 bv = wp[ni * 32];
                mma_f16(acc[0][ni], a0[0], a0[1], a0[2], a0[3], bv.x, bv.y);
                mma_f16(acc[1][ni], a1[0], a1[1], a1[2], a1[3], bv.x, bv.y);
                mma_f16(acc[0][ni], a2[0], a2[1], a2[2], a2[3], bv.z, bv.w);
                mma_f16(acc[1][ni], a3[0], a3[1], a3[2], a3[3], bv.z, bv.w);
            }
        }

        // stage A(s+1)
        if (more) {
            *(uint4*)(A_buf[nbuf] + pix * PADP + c8 * 4) =
                lerp8h(lt, rt, lb, rb, fy2, fx2);
        }

        // ---- MMA half kh=1 (chunk 2s+1) ----
        {
            const uint4* __restrict__ wp1 = wp + 1024;
            uint32_t a0[4], a1[4], a2[4], a3[4];
            ldsm_x4(a0, a_base + 16u * 4u);
            ldsm_x4(a1, a_base + (uint32_t)((16 * PADP + 16) * 4));
            ldsm_x4(a2, a_base + 24u * 4u);
            ldsm_x4(a3, a_base + (uint32_t)((16 * PADP + 24) * 4));
            #pragma unroll
            for (int ni = 0; ni < 4; ni++) {
                uint4 bv = wp1[ni * 32];
                mma_f16(acc[0][ni], a0[0], a0[1], a0[2], a0[3], bv.x, bv.y);
                mma_f16(acc[1][ni], a1[0], a1[1], a1[2], a1[3], bv.x, bv.y);
                mma_f16(acc[0][ni], a2[0], a2[1], a2[2], a2[3], bv.z, bv.w);
                mma_f16(acc[1][ni], a3[0], a3[1], a3[2], a3[3], bv.z, bv.w);
            }
        }
    }

    // ---- epilogue: add bias, store ----
    #pragma unroll
    for (int mi = 0; mi < 2; mi++) {
        const int row0 = mi * 16 + gq;
        float* o0 = out + ((size_t)pbase + row0) * F_;
        float* o1 = o0 + 8 * F_;
        #pragma unroll
        for (int ni = 0; ni < 4; ni++) {
            const int f = wid * 32 + ni * 8 + tq * 2;
            const float2 bb = *(const float2*)(bias + f);
            float2 r0, r1;
            r0.x = acc[mi][ni][0] + bb.x;
            r0.y = acc[mi][ni][1] + bb.y;
            r1.x = acc[mi][ni][2] + bb.x;
            r1.y = acc[mi][ni][3] + bb.y;
            *(float2*)(o0 + f) = r0;
            *(float2*)(o1 + f) = r1;
        }
    }
}

}  // namespace

extern "C" void kernel_launch(void* const* d_in, const int* in_sizes, int n_in,
                              void* d_out, int out_size) {
    (void)in_sizes; (void)n_in; (void)out_size;
    const float* x    = (const float*)d_in[0];   // (8,64,64,128)
    const float* offs = (const float*)d_in[1];   // (8,64,64,18)
    const float* Wt   = (const float*)d_in[2];   // (9,128,256)
    const float* bias = (const float*)d_in[3];   // (256,)
    float* out = (float*)d_out;                  // (8,64,64,256)

    cudaFuncSetAttribute(deform_mma_kernel,
                         cudaFuncAttributeMaxDynamicSharedMemorySize, SMEM_BYTES);

    prep_kernel<<<2048 + (36 * W_CH) / 256, 256>>>(x, Wt);
    deform_mma_kernel<<<(B_ * H_ * W_ * W_ ? 1024 : 1024), THREADS, SMEM_BYTES>>>(offs, bias, out);
}